// round 14
// baseline (speedup 1.0000x reference)
#include <cuda_runtime.h>
#include <cuda_bf16.h>
#include <float.h>
#include <math.h>
#include <stdint.h>

// ---------------- problem constants ----------------
constexpr int   Bn   = 16;
constexpr int   Nn   = 33600;
constexpr int   Cc   = 80;
constexpr int   MAXN = 100;
constexpr float THR  = 0.05f;
constexpr float IOUT = 0.65f;

// histogram constants: bucket = (bits - BASE) >> 14
constexpr unsigned BASE = 0x3D000000u;   // below bits(0.05)=0x3D4CCCCD
constexpr int      HB    = 2560;         // (0x3F800000-BASE)>>14
constexpr int      CAP   = 1024;         // candidate capacity per batch

constexpr int   TPB      = 960;                  // 30 warps
constexpr int   ANCH     = 240;                  // anchors per score CTA (chunk)
constexpr int   CHB      = Nn / ANCH;            // 140 chunks per batch (exact)
constexpr int   SCORE_CTAS = Bn * CHB;           // 2240
constexpr int   HBPAD    = TPB * 3;              // 2880 >= HB
constexpr int   GRP      = 20;                   // chunks per consume group
constexpr int   NGRP     = CHB / GRP;            // 7
constexpr int   GRP_V    = GRP * ANCH / 2;       // 2400 uint4 per group

// ---------------- device scratch ----------------
__device__ uint2        g_sl[Bn * Nn];        // {score_bits (0 if <THR), label}
__device__ volatile int g_cflag[SCORE_CTAS];  // chunk-complete flags; reset by selects

// intra-warp inclusive suffix sum over lanes [lane..N-1]
template<int NL>
__device__ __forceinline__ unsigned warp_suffix_sumN(unsigned v, int lane) {
#pragma unroll
    for (int o = 1; o < NL; o <<= 1) {
        unsigned u = __shfl_down_sync(0xffffffffu, v, o);
        if (lane + o < NL) v += u;
    }
    return v;
}

__global__ void __launch_bounds__(TPB, 2)
k_all(const float* __restrict__ cls,
      const float* __restrict__ obj,
      const float* __restrict__ bbox,
      const float* __restrict__ priors,
      float* __restrict__ out,
      int write_keep) {
    __shared__ unsigned           hist[HBPAD];
    __shared__ unsigned           csum[TPB];
    __shared__ unsigned           wsum[32];
    __shared__ unsigned long long cand[CAP];
    __shared__ int                spos[128];
    __shared__ int                misc[2];
    __shared__ float4             bx4[MAXN];
    __shared__ float              ars[MAXN];
    __shared__ float              sss[MAXN];
    __shared__ int                lls[MAXN];
    __shared__ unsigned           sup[MAXN][4];
    __shared__ unsigned           kin[4];
    __shared__ unsigned           kout[4];

    int bid = blockIdx.x;
    int tid = threadIdx.x;

    if (bid >= Bn) {
        // ================= score role: one chunk of 240 anchors =================
        int chunk = bid - Bn;
        int a     = chunk * ANCH + (tid >> 2);   // global anchor
        int sub   = tid & 3;

        const float4* p = reinterpret_cast<const float4*>(cls + (size_t)a * Cc + sub * 20);
        float mx = -FLT_MAX;
        int   mi = 0;
#pragma unroll
        for (int i = 0; i < 5; i++) {
            float4 v = p[i];
            int base = sub * 20 + i * 4;
            if (v.x > mx) { mx = v.x; mi = base; }
            if (v.y > mx) { mx = v.y; mi = base + 1; }
            if (v.z > mx) { mx = v.z; mi = base + 2; }
            if (v.w > mx) { mx = v.w; mi = base + 3; }
        }
#pragma unroll
        for (int off = 1; off < 4; off <<= 1) {
            float om  = __shfl_xor_sync(0xffffffffu, mx, off);
            int   omi = __shfl_xor_sync(0xffffffffu, mi, off);
            if (om > mx || (om == mx && omi < mi)) { mx = om; mi = omi; }
        }
        if (sub == 0) {
            float o = obj[a];
            float s = (1.0f / (1.0f + __expf(-mx))) * (1.0f / (1.0f + __expf(-o)));
            unsigned bits = (s >= THR) ? __float_as_uint(s) : 0u;
            g_sl[a] = make_uint2(bits, (unsigned)mi);
        }
        __syncthreads();
        if (tid == 0) {
            __threadfence();          // release g_sl writes
            g_cflag[chunk] = 1;
        }
        return;
    }

    // ================= select + NMS role (bids 0..15) =================
    int b    = bid;
    int lane = tid & 31;
    int wid  = tid >> 5;

    // init smem
#pragma unroll
    for (int k = 0; k < HBPAD / TPB; k++) hist[tid + k * TPB] = 0u;
    if (tid == 0) { misc[0] = 0; misc[1] = 0; }
    if (tid < 4)  kin[tid] = 0u;
    if (tid < 128) spos[tid] = -1;
    __syncthreads();

    // --- incremental histogram: consume chunk groups as they complete ---
    int cb = b * CHB;
    for (int g = 0; g < NGRP; g++) {
        if (tid == 0) {
            for (int k = 0; k < GRP; k++) {
                while (g_cflag[cb + g * GRP + k] == 0) __nanosleep(128);
            }
        }
        __syncthreads();   // orders data reads after flag observation
        const uint4* gp = reinterpret_cast<const uint4*>(
            g_sl + (size_t)b * Nn + g * (GRP * ANCH));
        for (int i = tid; i < GRP_V; i += TPB) {
            uint4 v = gp[i];
            if (v.x) {
                unsigned bk = (v.x - BASE) >> 14;
                if (bk >= (unsigned)HB) bk = HB - 1;
                atomicAdd(&hist[bk], 1u);
            }
            if (v.z) {
                unsigned bk = (v.z - BASE) >> 14;
                if (bk >= (unsigned)HB) bk = HB - 1;
                atomicAdd(&hist[bk], 1u);
            }
        }
    }
    __syncthreads();

    // --- suffix scan over TPB chunk sums (3 buckets/thread) ---
    unsigned cs = hist[tid * 3] + hist[tid * 3 + 1] + hist[tid * 3 + 2];
    unsigned suf = warp_suffix_sumN<32>(cs, lane);
    if (lane == 0) wsum[wid] = suf;
    __syncthreads();
    if (wid == 0) {
        unsigned wv = (lane < TPB / 32) ? wsum[lane] : 0u;
        wsum[lane] = warp_suffix_sumN<TPB / 32>(wv, lane);
    }
    __syncthreads();
    unsigned suffTotal = suf + ((wid < TPB / 32 - 1) ? wsum[wid + 1] : 0u);
    csum[tid] = suffTotal;
    __syncthreads();
    if (suffTotal >= (unsigned)MAXN &&
        (tid == TPB - 1 || csum[tid + 1] < (unsigned)MAXN))
        misc[0] = tid;
    __syncthreads();
    if (tid == 0) {
        int c = misc[0];
        int cum = (c < TPB - 1) ? (int)csum[c + 1] : 0;
        int bstart = c * 3;
        int bb = bstart + 2;
        for (; bb >= bstart; bb--) {
            cum += (int)hist[bb];
            if (cum >= MAXN) break;
        }
        int bucket = (bb < bstart) ? bstart : bb;
        misc[0] = (int)(BASE + ((unsigned)bucket << 14));
    }
    __syncthreads();
    unsigned TB = (unsigned)misc[0];

    // --- compact (one L2-hot pass over the batch) ---
    const uint4* sp = reinterpret_cast<const uint4*>(g_sl + (size_t)b * Nn);
#pragma unroll 2
    for (int i = tid; i < Nn / 2; i += TPB) {
        uint4 v = sp[i];
        if (v.x >= TB) {
            int pos = atomicAdd(&misc[1], 1);
            if (pos < CAP)
                cand[pos] = ((unsigned long long)v.x << 32) | (unsigned)(~(2 * i));
        }
        if (v.z >= TB) {
            int pos = atomicAdd(&misc[1], 1);
            if (pos < CAP)
                cand[pos] = ((unsigned long long)v.z << 32) | (unsigned)(~(2 * i + 1));
        }
    }
    __syncthreads();
    int cnt = misc[1]; if (cnt > CAP) cnt = CAP;

    // --- exact rank (keys unique) ---
    for (int c0 = tid; c0 < cnt; c0 += TPB) {
        unsigned long long mk = cand[c0];
        int r = 0;
        for (int j = 0; j < cnt; j++) r += (cand[j] > mk);
        if (r < 128) spos[r] = c0;
    }
    __syncthreads();

    // --- decode winners ---
    if (tid < MAXN) {
        sup[tid][0] = 0u; sup[tid][1] = 0u; sup[tid][2] = 0u; sup[tid][3] = 0u;
        int p = spos[tid];
        if (p >= 0) {
            unsigned long long key = cand[p];
            int idx = (int)(~(unsigned)(key & 0xffffffffu));
            float4 pr = reinterpret_cast<const float4*>(priors)[idx];
            float4 bp = reinterpret_cast<const float4*>(bbox)[(size_t)b * Nn + idx];
            float cx = bp.x * pr.z + pr.x;
            float cy = bp.y * pr.w + pr.y;
            float w  = __expf(bp.z) * pr.z;
            float h  = __expf(bp.w) * pr.w;
            bx4[tid] = make_float4(cx - 0.5f * w, cy - 0.5f * h,
                                   cx + 0.5f * w, cy + 0.5f * h);
            ars[tid] = w * h;
            sss[tid] = __uint_as_float((unsigned)(key >> 32));
            lls[tid] = (int)g_sl[(size_t)b * Nn + idx].y;
            atomicOr(&kin[tid >> 5], 1u << (tid & 31));
        } else {
            bx4[tid] = make_float4(0.f, 0.f, 0.f, 0.f);
            ars[tid] = 0.f; sss[tid] = 0.f; lls[tid] = -1;
        }
    }
    __syncthreads();

    // --- parallel pairwise suppression matrix ---
    for (int p = tid; p < MAXN * MAXN; p += TPB) {
        int i = p / MAXN;
        int r = p - i * MAXN;
        if (r > i) {
            int li = lls[i];
            if (li >= 0 && li == lls[r]) {
                float4 bi = bx4[i];
                float4 br = bx4[r];
                float ix1 = fmaxf(br.x, bi.x);
                float iy1 = fmaxf(br.y, bi.y);
                float ix2 = fminf(br.z, bi.z);
                float iy2 = fminf(br.w, bi.w);
                float inter = fmaxf(ix2 - ix1, 0.0f) * fmaxf(iy2 - iy1, 0.0f);
                float uni   = ars[i] + ars[r] - inter;
                if (inter / (uni + 1e-8f) >= IOUT)
                    atomicOr(&sup[i][r >> 5], 1u << (r & 31));
            }
        }
    }
    __syncthreads();

    // --- greedy scan: software-pipelined register bit logic ---
    if (tid == 0) {
        unsigned k0 = kin[0], k1 = kin[1], k2 = kin[2], k3 = kin[3];
        unsigned n0 = sup[0][0], n1 = sup[0][1], n2 = sup[0][2], n3 = sup[0][3];
        for (int i = 0; i < MAXN - 1; i++) {
            unsigned c0 = n0, c1 = n1, c2 = n2, c3 = n3;
            n0 = sup[i + 1][0]; n1 = sup[i + 1][1];
            n2 = sup[i + 1][2]; n3 = sup[i + 1][3];
            unsigned kw = (i < 32) ? k0 : (i < 64) ? k1 : (i < 96) ? k2 : k3;
            if ((kw >> (i & 31)) & 1u) {
                k0 &= ~c0; k1 &= ~c1; k2 &= ~c2; k3 &= ~c3;
            }
        }
        kout[0] = k0; kout[1] = k1; kout[2] = k2; kout[3] = k3;
    }
    __syncthreads();

    // --- write output ---
    if (tid < MAXN) {
        bool kept = (kout[tid >> 5] >> (tid & 31)) & 1u;
        float* row = out + ((size_t)b * MAXN + tid) * 6;
        if (kept) {
            float4 bb = bx4[tid];
            row[0] = bb.x; row[1] = bb.y; row[2] = bb.z; row[3] = bb.w;
            row[4] = sss[tid]; row[5] = (float)lls[tid];
        } else {
            row[0] = 0.0f; row[1] = 0.0f; row[2] = 0.0f; row[3] = 0.0f;
            row[4] = 0.0f; row[5] = -1.0f;
        }
        if (write_keep)
            out[(size_t)Bn * MAXN * 6 + b * MAXN + tid] = kept ? 1.0f : 0.0f;
    }

    // --- reset this batch's chunk flags for the next graph replay ---
    if (tid < CHB) g_cflag[cb + tid] = 0;
}

// ---------------- host launcher ----------------
extern "C" void kernel_launch(void* const* d_in, const int* in_sizes, int n_in,
                              void* d_out, int out_size) {
    const float* cls    = nullptr;
    const float* bbox   = nullptr;
    const float* obj    = nullptr;
    const float* priors = nullptr;
    for (int i = 0; i < n_in; i++) {
        int sz = in_sizes[i];
        if      (sz == Bn * Nn * Cc) cls    = (const float*)d_in[i];
        else if (sz == Bn * Nn * 4)  bbox   = (const float*)d_in[i];
        else if (sz == Bn * Nn)      obj    = (const float*)d_in[i];
        else if (sz == Nn * 4)       priors = (const float*)d_in[i];
    }
    float* out = (float*)d_out;
    int write_keep = (out_size >= Bn * MAXN * 6 + Bn * MAXN) ? 1 : 0;

    k_all<<<Bn + SCORE_CTAS, TPB>>>(cls, obj, bbox, priors, out, write_keep);
}

// round 17
// speedup vs baseline: 1.5074x; 1.5074x over previous
#include <cuda_runtime.h>
#include <cuda_bf16.h>
#include <float.h>
#include <math.h>
#include <stdint.h>

// ---------------- problem constants ----------------
constexpr int   Bn   = 16;
constexpr int   Nn   = 33600;
constexpr int   Cc   = 80;
constexpr int   MAXN = 100;
constexpr float THR  = 0.05f;
constexpr float IOUT = 0.65f;

// histogram constants: bucket = (bits - BASE) >> 14
constexpr unsigned BASE  = 0x3D000000u;  // below bits(0.05)=0x3D4CCCCD
constexpr int      HB    = 2560;         // (0x3F800000-BASE)>>14
constexpr int      HBPAD = 3072;         // 1024*3 for the scan
constexpr int      CAP   = 1024;         // candidate capacity per batch

// ---------------- device scratch ----------------
__device__ uint2 g_sl[Bn * Nn];   // {score_bits (0 if <THR), label}

// ---------------- kernel 1: sigmoid + max/argmax + packed store (clean, proven 30.8us) ----------------
// 4 lanes per anchor; each lane reads 20 floats (5x float4), default cache policy.
__global__ void k_score(const float* __restrict__ cls,
                        const float* __restrict__ obj) {
    int t   = blockIdx.x * blockDim.x + threadIdx.x;
    int a   = t >> 2;          // anchor
    int sub = t & 3;
    if (a >= Bn * Nn) return;

    const float4* p = reinterpret_cast<const float4*>(cls + (size_t)a * Cc + sub * 20);
    float mx = -FLT_MAX;
    int   mi = 0;
#pragma unroll
    for (int i = 0; i < 5; i++) {
        float4 v = p[i];
        int base = sub * 20 + i * 4;
        if (v.x > mx) { mx = v.x; mi = base; }
        if (v.y > mx) { mx = v.y; mi = base + 1; }
        if (v.z > mx) { mx = v.z; mi = base + 2; }
        if (v.w > mx) { mx = v.w; mi = base + 3; }
    }
#pragma unroll
    for (int off = 1; off < 4; off <<= 1) {
        float om  = __shfl_xor_sync(0xffffffffu, mx, off);
        int   omi = __shfl_xor_sync(0xffffffffu, mi, off);
        if (om > mx || (om == mx && omi < mi)) { mx = om; mi = omi; }
    }
    if (sub == 0) {
        float o = obj[a];
        float s = (1.0f / (1.0f + __expf(-mx))) * (1.0f / (1.0f + __expf(-o)));
        unsigned bits = (s >= THR) ? __float_as_uint(s) : 0u;
        g_sl[a] = make_uint2(bits, (unsigned)mi);
    }
}

// intra-warp inclusive suffix sum over 32 lanes
__device__ __forceinline__ unsigned warp_suffix_sum(unsigned v, int lane) {
#pragma unroll
    for (int o = 1; o < 32; o <<= 1) {
        unsigned u = __shfl_down_sync(0xffffffffu, v, o);
        if (lane + o < 32) v += u;
    }
    return v;
}

// ---------------- kernel 2: smem hist + scan + compact + rank + decode + matrix NMS ----------------
__global__ void __launch_bounds__(1024, 1)
k_selnms(const float* __restrict__ bbox,
         const float* __restrict__ priors,
         float* __restrict__ out,
         int write_keep) {
    __shared__ unsigned           hist[HBPAD];
    __shared__ unsigned           csum[1024];
    __shared__ unsigned           wsum[32];
    __shared__ unsigned long long cand[CAP];
    __shared__ int                spos[128];
    __shared__ int                misc[2];
    __shared__ float4             bx4[MAXN];
    __shared__ float              ars[MAXN];
    __shared__ float              sss[MAXN];
    __shared__ int                lls[MAXN];
    __shared__ unsigned           sup[MAXN][4];
    __shared__ unsigned           kin[4];
    __shared__ unsigned           kout[4];

    int b    = blockIdx.x;
    int tid  = threadIdx.x;
    int lane = tid & 31;
    int wid  = tid >> 5;

    // init smem
#pragma unroll
    for (int k = 0; k < HBPAD / 1024; k++) hist[tid + k * 1024] = 0u;
    if (tid == 0) { misc[0] = 0; misc[1] = 0; }
    if (tid < 4)  kin[tid] = 0u;
    if (tid < 128) spos[tid] = -1;
    __syncthreads();

    const uint4* sp = reinterpret_cast<const uint4*>(g_sl + (size_t)b * Nn);

    // pass 1: smem histogram
#pragma unroll 2
    for (int i = tid; i < Nn / 2; i += 1024) {
        uint4 v = sp[i];
        if (v.x) {
            unsigned bk = (v.x - BASE) >> 14;
            if (bk >= (unsigned)HB) bk = HB - 1;
            atomicAdd(&hist[bk], 1u);
        }
        if (v.z) {
            unsigned bk = (v.z - BASE) >> 14;
            if (bk >= (unsigned)HB) bk = HB - 1;
            atomicAdd(&hist[bk], 1u);
        }
    }
    __syncthreads();

    // suffix scan over 1024 chunk sums (3 buckets/thread)
    unsigned cs = hist[tid * 3] + hist[tid * 3 + 1] + hist[tid * 3 + 2];
    unsigned suf = warp_suffix_sum(cs, lane);
    if (lane == 0) wsum[wid] = suf;
    __syncthreads();
    if (wid == 0) {
        unsigned wv = wsum[lane];
        wsum[lane] = warp_suffix_sum(wv, lane);
    }
    __syncthreads();
    unsigned suffTotal = suf + ((wid < 31) ? wsum[wid + 1] : 0u);
    csum[tid] = suffTotal;
    __syncthreads();
    if (suffTotal >= (unsigned)MAXN &&
        (tid == 1023 || csum[tid + 1] < (unsigned)MAXN))
        misc[0] = tid;
    __syncthreads();
    if (tid == 0) {
        int c = misc[0];
        int cum = (c < 1023) ? (int)csum[c + 1] : 0;
        int bstart = c * 3;
        int bb = bstart + 2;
        for (; bb >= bstart; bb--) {
            cum += (int)hist[bb];
            if (cum >= MAXN) break;
        }
        int bucket = (bb < bstart) ? bstart : bb;
        misc[0] = (int)(BASE + ((unsigned)bucket << 14));
    }
    __syncthreads();
    unsigned TB = (unsigned)misc[0];

    // pass 2: compact (L2-hot re-read)
#pragma unroll 2
    for (int i = tid; i < Nn / 2; i += 1024) {
        uint4 v = sp[i];
        if (v.x >= TB) {
            int pos = atomicAdd(&misc[1], 1);
            if (pos < CAP)
                cand[pos] = ((unsigned long long)v.x << 32) | (unsigned)(~(2 * i));
        }
        if (v.z >= TB) {
            int pos = atomicAdd(&misc[1], 1);
            if (pos < CAP)
                cand[pos] = ((unsigned long long)v.z << 32) | (unsigned)(~(2 * i + 1));
        }
    }
    __syncthreads();
    int cnt = misc[1]; if (cnt > CAP) cnt = CAP;

    // exact rank (keys unique: ~idx in low bits)
    if (tid < cnt) {
        unsigned long long mk = cand[tid];
        int r = 0;
        for (int j = 0; j < cnt; j++) r += (cand[j] > mk);
        if (r < 128) spos[r] = tid;
    }
    __syncthreads();

    // decode winners
    if (tid < MAXN) {
        sup[tid][0] = 0u; sup[tid][1] = 0u; sup[tid][2] = 0u; sup[tid][3] = 0u;
        int p = spos[tid];
        if (p >= 0) {
            unsigned long long key = cand[p];
            int idx = (int)(~(unsigned)(key & 0xffffffffu));
            float4 pr = reinterpret_cast<const float4*>(priors)[idx];
            float4 bp = reinterpret_cast<const float4*>(bbox)[(size_t)b * Nn + idx];
            float cx = bp.x * pr.z + pr.x;
            float cy = bp.y * pr.w + pr.y;
            float w  = __expf(bp.z) * pr.z;
            float h  = __expf(bp.w) * pr.w;
            bx4[tid] = make_float4(cx - 0.5f * w, cy - 0.5f * h,
                                   cx + 0.5f * w, cy + 0.5f * h);
            ars[tid] = w * h;
            sss[tid] = __uint_as_float((unsigned)(key >> 32));
            lls[tid] = (int)g_sl[(size_t)b * Nn + idx].y;
            atomicOr(&kin[tid >> 5], 1u << (tid & 31));
        } else {
            bx4[tid] = make_float4(0.f, 0.f, 0.f, 0.f);
            ars[tid] = 0.f; sss[tid] = 0.f; lls[tid] = -1;
        }
    }
    __syncthreads();

    // parallel pairwise suppression matrix (r > i, same label, IoU >= thr)
    for (int p = tid; p < MAXN * MAXN; p += 1024) {
        int i = p / MAXN;
        int r = p - i * MAXN;
        if (r > i) {
            int li = lls[i];
            if (li >= 0 && li == lls[r]) {
                float4 bi = bx4[i];
                float4 br = bx4[r];
                float ix1 = fmaxf(br.x, bi.x);
                float iy1 = fmaxf(br.y, bi.y);
                float ix2 = fminf(br.z, bi.z);
                float iy2 = fminf(br.w, bi.w);
                float inter = fmaxf(ix2 - ix1, 0.0f) * fmaxf(iy2 - iy1, 0.0f);
                float uni   = ars[i] + ars[r] - inter;
                if (inter / (uni + 1e-8f) >= IOUT)
                    atomicOr(&sup[i][r >> 5], 1u << (r & 31));
            }
        }
    }
    __syncthreads();

    // greedy scan: software-pipelined register bit logic on one thread
    if (tid == 0) {
        unsigned k0 = kin[0], k1 = kin[1], k2 = kin[2], k3 = kin[3];
        unsigned n0 = sup[0][0], n1 = sup[0][1], n2 = sup[0][2], n3 = sup[0][3];
        for (int i = 0; i < MAXN - 1; i++) {
            unsigned c0 = n0, c1 = n1, c2 = n2, c3 = n3;
            n0 = sup[i + 1][0]; n1 = sup[i + 1][1];
            n2 = sup[i + 1][2]; n3 = sup[i + 1][3];
            unsigned kw = (i < 32) ? k0 : (i < 64) ? k1 : (i < 96) ? k2 : k3;
            if ((kw >> (i & 31)) & 1u) {
                k0 &= ~c0; k1 &= ~c1; k2 &= ~c2; k3 &= ~c3;
            }
        }
        kout[0] = k0; kout[1] = k1; kout[2] = k2; kout[3] = k3;
    }
    __syncthreads();

    // write output
    if (tid < MAXN) {
        bool kept = (kout[tid >> 5] >> (tid & 31)) & 1u;
        float* row = out + ((size_t)b * MAXN + tid) * 6;
        if (kept) {
            float4 bb = bx4[tid];
            row[0] = bb.x; row[1] = bb.y; row[2] = bb.z; row[3] = bb.w;
            row[4] = sss[tid]; row[5] = (float)lls[tid];
        } else {
            row[0] = 0.0f; row[1] = 0.0f; row[2] = 0.0f; row[3] = 0.0f;
            row[4] = 0.0f; row[5] = -1.0f;
        }
        if (write_keep)
            out[(size_t)Bn * MAXN * 6 + b * MAXN + tid] = kept ? 1.0f : 0.0f;
    }
}

// ---------------- host launcher ----------------
extern "C" void kernel_launch(void* const* d_in, const int* in_sizes, int n_in,
                              void* d_out, int out_size) {
    const float* cls    = nullptr;
    const float* bbox   = nullptr;
    const float* obj    = nullptr;
    const float* priors = nullptr;
    for (int i = 0; i < n_in; i++) {
        int sz = in_sizes[i];
        if      (sz == Bn * Nn * Cc) cls    = (const float*)d_in[i];
        else if (sz == Bn * Nn * 4)  bbox   = (const float*)d_in[i];
        else if (sz == Bn * Nn)      obj    = (const float*)d_in[i];
        else if (sz == Nn * 4)       priors = (const float*)d_in[i];
    }
    float* out = (float*)d_out;
    int write_keep = (out_size >= Bn * MAXN * 6 + Bn * MAXN) ? 1 : 0;

    int total_threads = Bn * Nn * 4;
    k_score<<<(total_threads + 255) / 256, 256>>>(cls, obj);
    k_selnms<<<Bn, 1024>>>(bbox, priors, out, write_keep);
}